// round 2
// baseline (speedup 1.0000x reference)
#include <cuda_runtime.h>
#include <cstdint>

// Problem constants: pred/target are [16,1,1024,1024] float32.
#define H 1024
#define W 1024
#define TOTAL (16u * 1024u * 1024u * 1u)   // 16777216 elements
#define W4 256                              // float4 per row

// LUT: softplus(z) over z in [-16,16], 4096 intervals (h = 1/128)
#define LUT_N 4096
#define LUT_SCALE 128.0f
#define LUT_OFFSET 2048.0f

#define GRID_B 2048
#define THREADS_B 256
#define ITERS_B 8          // 2048*256*8 float4 = 4,194,304 = TOTAL/4
#define STRIDE_F4 (GRID_B * THREADS_B)      // 524288 float4 per iteration step

__device__ float2 g_lut[LUT_N + 1];
__device__ float  g_partials[GRID_B];

// ---------------------------------------------------------------------------
// Kernel A: build softplus LUT (value, delta-to-next) in global memory.
// ---------------------------------------------------------------------------
__device__ __forceinline__ float softplus_ref(float z) {
    float a = fabsf(z);
    return fmaxf(z, 0.0f) + log1pf(expf(-a));
}

__global__ void build_lut_kernel() {
    for (int i = threadIdx.x; i <= LUT_N; i += blockDim.x) {
        float z0 = ((float)i       - LUT_OFFSET) * (1.0f / LUT_SCALE);
        float z1 = ((float)(i + 1) - LUT_OFFSET) * (1.0f / LUT_SCALE);
        float f0 = softplus_ref(z0);
        float f1 = softplus_ref(z1);
        g_lut[i] = make_float2(f0, f1 - f0);
    }
}

// ---------------------------------------------------------------------------
// Kernel B: fused dilate + weighted BCE + per-block reduction.
// ---------------------------------------------------------------------------
__device__ __forceinline__ float elem_loss(float x, float t, unsigned dil_bits,
                                           const float2* __restrict__ lut,
                                           float acc) {
    float dil  = __uint_as_float(dil_bits);          // exactly 0.0f or 1.0f
    float s    = fmaf(t, -2.0f, 1.0f);               // +1 / -1
    float z    = s * x;                              // softplus argument
    float idxf = fmaf(z, LUT_SCALE, LUT_OFFSET);     // in [0, 4096)
    int   i    = (int)idxf;
    float frac = idxf - (float)i;
    float2 e   = lut[i];
    float sp   = fmaf(frac, e.y, e.x);
    float w    = fmaf(t, 15.0f, fmaf(dil, 4.0f, 1.0f)); // 1 / 5 / 20
    return fmaf(w, sp, acc);
}

__global__ void __launch_bounds__(THREADS_B)
main_kernel(const float* __restrict__ pred, const float* __restrict__ target) {
    __shared__ float2 lut[LUT_N + 1];
    __shared__ float  sred[THREADS_B];

    const int tid = threadIdx.x;
    const int bid = blockIdx.x;

    // stage LUT into shared
    for (int i = tid; i <= LUT_N; i += THREADS_B) lut[i] = g_lut[i];
    __syncthreads();

    // Thread geometry: float4 index i4 = bid*256 + tid + k*STRIDE_F4.
    // STRIDE_F4 % 256 == 0  -> column (i4 % 256) == tid  (loop-invariant).
    // rows advance by 2048 per iter; 2048 % 1024 == 0 -> r = bid & 1023 (loop-invariant).
    const int  r        = bid & (H - 1);
    const int  lane     = tid & 31;
    const bool leftLane  = (lane == 0);
    const bool rightLane = (lane == 31);
    const bool imgLeft   = (tid == 0);          // column 0 of the row
    const bool imgRight  = (tid == THREADS_B - 1); // last float4 of the row

    size_t baseF = (size_t)bid * (size_t)(THREADS_B * 4) + (size_t)tid * 4;
    const float* pp  = pred   + baseF;
    const float* cur = target + baseF;
    const float* up  = cur + ((r > 0)     ? -(int)W : 0);   // clamp: duplicate row
    const float* dn  = cur + ((r < H - 1) ?  (int)W : 0);

    const size_t STRIDE_F = (size_t)STRIDE_F4 * 4;

    float acc = 0.0f;

#pragma unroll
    for (int k = 0; k < ITERS_B; k++) {
        float4 p  = *reinterpret_cast<const float4*>(pp);
        float4 tc = *reinterpret_cast<const float4*>(cur);
        float4 tu = *reinterpret_cast<const float4*>(up);
        float4 td = *reinterpret_cast<const float4*>(dn);

        // vertical OR (== 3-row max for {0.0f,1.0f} data)
        unsigned v0 = __float_as_uint(tc.x) | __float_as_uint(tu.x) | __float_as_uint(td.x);
        unsigned v1 = __float_as_uint(tc.y) | __float_as_uint(tu.y) | __float_as_uint(td.y);
        unsigned v2 = __float_as_uint(tc.z) | __float_as_uint(tu.z) | __float_as_uint(td.z);
        unsigned v3 = __float_as_uint(tc.w) | __float_as_uint(tu.w) | __float_as_uint(td.w);

        // horizontal neighbors across lanes
        unsigned vL = __shfl_up_sync(0xffffffffu, v3, 1);
        unsigned vR = __shfl_down_sync(0xffffffffu, v0, 1);
        if (leftLane) {
            unsigned a = 0u;
            if (!imgLeft)
                a = __float_as_uint(cur[-1]) | __float_as_uint(up[-1]) | __float_as_uint(dn[-1]);
            vL = a;
        }
        if (rightLane) {
            unsigned a = 0u;
            if (!imgRight)
                a = __float_as_uint(cur[4]) | __float_as_uint(up[4]) | __float_as_uint(dn[4]);
            vR = a;
        }

        // horizontal OR -> full 3x3 dilation bits
        unsigned d0 = vL | v0 | v1;
        unsigned d1 = v0 | v1 | v2;
        unsigned d2 = v1 | v2 | v3;
        unsigned d3 = v2 | v3 | vR;

        acc = elem_loss(p.x, tc.x, d0, lut, acc);
        acc = elem_loss(p.y, tc.y, d1, lut, acc);
        acc = elem_loss(p.z, tc.z, d2, lut, acc);
        acc = elem_loss(p.w, tc.w, d3, lut, acc);

        pp += STRIDE_F; cur += STRIDE_F; up += STRIDE_F; dn += STRIDE_F;
    }

    // deterministic block reduction
    sred[tid] = acc;
    __syncthreads();
#pragma unroll
    for (int s = THREADS_B / 2; s > 0; s >>= 1) {
        if (tid < s) sred[tid] += sred[tid + s];
        __syncthreads();
    }
    if (tid == 0) g_partials[bid] = sred[0];
}

// ---------------------------------------------------------------------------
// Kernel C: deterministic final reduction of 2048 partials -> mean.
// ---------------------------------------------------------------------------
__global__ void __launch_bounds__(1024)
reduce_kernel(float* __restrict__ out) {
    __shared__ float s[1024];
    int tid = threadIdx.x;
    s[tid] = g_partials[tid] + g_partials[tid + 1024];
    __syncthreads();
#pragma unroll
    for (int st = 512; st > 0; st >>= 1) {
        if (tid < st) s[tid] += s[tid + st];
        __syncthreads();
    }
    if (tid == 0) out[0] = s[0] * (1.0f / (float)TOTAL);
}

// ---------------------------------------------------------------------------
extern "C" void kernel_launch(void* const* d_in, const int* in_sizes, int n_in,
                              void* d_out, int out_size) {
    const float* pred   = (const float*)d_in[0];
    const float* target = (const float*)d_in[1];
    (void)in_sizes; (void)n_in; (void)out_size;

    build_lut_kernel<<<1, 256>>>();
    main_kernel<<<GRID_B, THREADS_B>>>(pred, target);
    reduce_kernel<<<1, 1024>>>((float*)d_out);
}

// round 3
// speedup vs baseline: 2.5187x; 2.5187x over previous
#include <cuda_runtime.h>
#include <cstdint>

// pred/target: [16,1,1024,1024] float32.
#define H 1024
#define W 1024
#define TOTAL (16u * 1024u * 1024u)
#define ROWS_PER_BLOCK 8
#define THREADS_B 256
#define GRID_B 2048            // 16*1024 rows / 8 rows per block
#define BLOCKS_PER_IMG 128     // 1024 / 8

__device__ float g_partials[GRID_B];

__device__ __forceinline__ uint4 load_u4(const float* p) {
    float4 f = *reinterpret_cast<const float4*>(p);
    uint4 u;
    u.x = __float_as_uint(f.x); u.y = __float_as_uint(f.y);
    u.z = __float_as_uint(f.z); u.w = __float_as_uint(f.w);
    return u;
}

// weighted BCE-with-logits for one element.
// losses = w * softplus(x*(1-2t)),  w = 1 + 4*dil + 15*t  (t,dil in {0,1})
__device__ __forceinline__ float elem_loss(float x, unsigned tbits, unsigned dbits,
                                           float acc) {
    float t   = __uint_as_float(tbits);
    float dil = __uint_as_float(dbits);
    float z   = x * fmaf(t, -2.0f, 1.0f);
    float e   = __expf(-fabsf(z));          // FMUL + MUFU.EX2
    float l   = __logf(1.0f + e);           // FADD + MUFU.LG2 + FMUL
    float sp  = fmaxf(z, 0.0f) + l;
    float w   = fmaf(t, 15.0f, fmaf(dil, 4.0f, 1.0f));
    return fmaf(w, sp, acc);
}

__global__ void __launch_bounds__(THREADS_B)
main_kernel(const float* __restrict__ pred, const float* __restrict__ target) {
    __shared__ float sred[THREADS_B / 32];

    const int tid  = threadIdx.x;
    const int bid  = blockIdx.x;
    const int lane = tid & 31;

    const int  rblk = bid & (BLOCKS_PER_IMG - 1);
    const bool topB = (rblk == 0);
    const bool botB = (rblk == BLOCKS_PER_IMG - 1);

    const bool lL = (lane == 0);
    const bool lR = (lane == 31);
    const bool iL = (tid == 0);                 // image left edge column
    const bool iR = (tid == THREADS_B - 1);     // image right edge column

    // bid*8192 + tid*4 == img*1M + r0*W + col
    const size_t base = (size_t)bid * (ROWS_PER_BLOCK * W) + (size_t)tid * 4;
    const float* tg = target + base;
    const float* pr = pred   + base;

    // rolling raw target rows (bit-patterns; values are exactly 0.0f / 1.0f)
    uint4 tp, tc, tn;
    tc = load_u4(tg);
    tp = topB ? tc : load_u4(tg - W);

    // rolling halo scalars for warp-edge lanes (column tid*4-1 / tid*4+4)
    unsigned sLp = 0u, sLc = 0u, sLn = 0u;
    unsigned sRp = 0u, sRc = 0u, sRn = 0u;
    if (lL && !iL) {
        sLc = __float_as_uint(tg[-1]);
        sLp = topB ? sLc : __float_as_uint(tg[-1 - W]);
    }
    if (lR && !iR) {
        sRc = __float_as_uint(tg[4]);
        sRp = topB ? sRc : __float_as_uint(tg[4 - W]);
    }

    float acc = 0.0f;

#pragma unroll
    for (int i = 0; i < ROWS_PER_BLOCK; i++) {
        // next target row (clamped at image bottom; only reachable when i==7)
        const int nOff = (i == ROWS_PER_BLOCK - 1 && botB) ? i * W : (i + 1) * W;
        const float* tgn = tg + nOff;
        tn = load_u4(tgn);
        if (lL && !iL) sLn = __float_as_uint(tgn[-1]);
        if (lR && !iR) sRn = __float_as_uint(tgn[4]);

        // pred row (streaming: single-use, evict-first)
        float4 p = __ldcs(reinterpret_cast<const float4*>(pr + i * W));

        // vertical OR == 3-row max for {0.0f,1.0f} bit patterns (LOP3)
        uint4 v;
        v.x = tp.x | tc.x | tn.x;
        v.y = tp.y | tc.y | tn.y;
        v.z = tp.z | tc.z | tn.z;
        v.w = tp.w | tc.w | tn.w;

        // horizontal neighbors across lanes
        unsigned vLs = __shfl_up_sync(0xffffffffu, v.w, 1);
        unsigned vRs = __shfl_down_sync(0xffffffffu, v.x, 1);
        unsigned vL = lL ? (sLp | sLc | sLn) : vLs;   // zeros at image edge
        unsigned vR = lR ? (sRp | sRc | sRn) : vRs;

        // full 3x3 dilation bits
        unsigned d0 = vL  | v.x | v.y;
        unsigned d1 = v.x | v.y | v.z;
        unsigned d2 = v.y | v.z | v.w;
        unsigned d3 = v.z | v.w | vR;

        acc = elem_loss(p.x, tc.x, d0, acc);
        acc = elem_loss(p.y, tc.y, d1, acc);
        acc = elem_loss(p.z, tc.z, d2, acc);
        acc = elem_loss(p.w, tc.w, d3, acc);

        // roll windows (full unroll -> register renaming, no MOVs)
        tp = tc; tc = tn;
        sLp = sLc; sLc = sLn;
        sRp = sRc; sRc = sRn;
    }

    // block reduction: warp shuffle tree, then one smem stage (deterministic)
#pragma unroll
    for (int s = 16; s > 0; s >>= 1)
        acc += __shfl_down_sync(0xffffffffu, acc, s);
    if (lane == 0) sred[tid >> 5] = acc;
    __syncthreads();
    if (tid == 0) {
        float r = 0.0f;
#pragma unroll
        for (int wrp = 0; wrp < THREADS_B / 32; wrp++) r += sred[wrp];
        g_partials[bid] = r;
    }
}

__global__ void __launch_bounds__(1024)
reduce_kernel(float* __restrict__ out) {
    __shared__ float s[1024];
    int tid = threadIdx.x;
    s[tid] = g_partials[tid] + g_partials[tid + 1024];
    __syncthreads();
#pragma unroll
    for (int st = 512; st > 0; st >>= 1) {
        if (tid < st) s[tid] += s[tid + st];
        __syncthreads();
    }
    if (tid == 0) out[0] = s[0] * (1.0f / (float)TOTAL);
}

extern "C" void kernel_launch(void* const* d_in, const int* in_sizes, int n_in,
                              void* d_out, int out_size) {
    const float* pred   = (const float*)d_in[0];
    const float* target = (const float*)d_in[1];
    (void)in_sizes; (void)n_in; (void)out_size;

    main_kernel<<<GRID_B, THREADS_B>>>(pred, target);
    reduce_kernel<<<1, 1024>>>((float*)d_out);
}

// round 5
// speedup vs baseline: 2.5222x; 1.0014x over previous
#include <cuda_runtime.h>
#include <cstdint>

// pred/target: [16,1,1024,1024] float32.
#define H 1024
#define W 1024
#define TOTAL (16u * 1024u * 1024u)
#define ROWS_PER_BLOCK 8
#define THREADS_B 256
#define GRID_B 2048            // 16*1024 rows / 8 rows per block
#define BLOCKS_PER_IMG 128     // 1024 / 8

__device__ float g_partials[GRID_B];
__device__ unsigned g_done = 0;     // completion counter; reset by last block

__device__ __forceinline__ uint4 load_u4(const float* p) {
    float4 f = *reinterpret_cast<const float4*>(p);
    uint4 u;
    u.x = __float_as_uint(f.x); u.y = __float_as_uint(f.y);
    u.z = __float_as_uint(f.z); u.w = __float_as_uint(f.w);
    return u;
}

// weighted BCE-with-logits for one element.
// losses = w * softplus(x*(1-2t)),  w = 1 + 4*dil + 15*t  (t,dil in {0,1})
__device__ __forceinline__ float elem_loss(float x, unsigned tbits, unsigned dbits,
                                           float acc) {
    float t   = __uint_as_float(tbits);
    float dil = __uint_as_float(dbits);
    float z   = x * fmaf(t, -2.0f, 1.0f);
    float e   = __expf(-fabsf(z));          // FMUL + MUFU.EX2
    float l   = __logf(1.0f + e);           // FADD + MUFU.LG2 + FMUL
    float sp  = fmaxf(z, 0.0f) + l;
    float w   = fmaf(t, 15.0f, fmaf(dil, 4.0f, 1.0f));
    return fmaf(w, sp, acc);
}

__global__ void __launch_bounds__(THREADS_B)
main_kernel(const float* __restrict__ pred, const float* __restrict__ target,
            float* __restrict__ out) {
    __shared__ float sred[THREADS_B / 32];
    __shared__ bool  s_last;

    const int tid  = threadIdx.x;
    const int bid  = blockIdx.x;
    const int lane = tid & 31;

    const int  rblk = bid & (BLOCKS_PER_IMG - 1);
    const bool topB = (rblk == 0);
    const bool botB = (rblk == BLOCKS_PER_IMG - 1);

    const bool lL = (lane == 0);
    const bool lR = (lane == 31);
    const bool iL = (tid == 0);                 // image left edge column
    const bool iR = (tid == THREADS_B - 1);     // image right edge column

    // bid*8192 + tid*4 == img*1M + r0*W + col
    const size_t base = (size_t)bid * (ROWS_PER_BLOCK * W) + (size_t)tid * 4;
    const float* tg = target + base;
    const float* pr = pred   + base;

    // rolling raw target rows (bit-patterns; values are exactly 0.0f / 1.0f)
    uint4 tp, tc, tn;
    tc = load_u4(tg);
    tp = topB ? tc : load_u4(tg - W);

    // rolling halo scalars for warp-edge lanes (column tid*4-1 / tid*4+4)
    unsigned sLp = 0u, sLc = 0u, sLn = 0u;
    unsigned sRp = 0u, sRc = 0u, sRn = 0u;
    if (lL && !iL) {
        sLc = __float_as_uint(tg[-1]);
        sLp = topB ? sLc : __float_as_uint(tg[-1 - W]);
    }
    if (lR && !iR) {
        sRc = __float_as_uint(tg[4]);
        sRp = topB ? sRc : __float_as_uint(tg[4 - W]);
    }

    float acc = 0.0f;

#pragma unroll
    for (int i = 0; i < ROWS_PER_BLOCK; i++) {
        // next target row (clamped at image bottom; only reachable when i==7)
        const int nOff = (i == ROWS_PER_BLOCK - 1 && botB) ? i * W : (i + 1) * W;
        const float* tgn = tg + nOff;
        tn = load_u4(tgn);
        if (lL && !iL) sLn = __float_as_uint(tgn[-1]);
        if (lR && !iR) sRn = __float_as_uint(tgn[4]);

        // pred row (streaming: single-use, evict-first)
        float4 p = __ldcs(reinterpret_cast<const float4*>(pr + i * W));

        // vertical OR == 3-row max for {0.0f,1.0f} bit patterns (LOP3)
        uint4 v;
        v.x = tp.x | tc.x | tn.x;
        v.y = tp.y | tc.y | tn.y;
        v.z = tp.z | tc.z | tn.z;
        v.w = tp.w | tc.w | tn.w;

        // horizontal neighbors across lanes
        unsigned vLs = __shfl_up_sync(0xffffffffu, v.w, 1);
        unsigned vRs = __shfl_down_sync(0xffffffffu, v.x, 1);
        unsigned vL = lL ? (sLp | sLc | sLn) : vLs;   // zeros at image edge
        unsigned vR = lR ? (sRp | sRc | sRn) : vRs;

        // full 3x3 dilation bits
        unsigned d0 = vL  | v.x | v.y;
        unsigned d1 = v.x | v.y | v.z;
        unsigned d2 = v.y | v.z | v.w;
        unsigned d3 = v.z | v.w | vR;

        acc = elem_loss(p.x, tc.x, d0, acc);
        acc = elem_loss(p.y, tc.y, d1, acc);
        acc = elem_loss(p.z, tc.z, d2, acc);
        acc = elem_loss(p.w, tc.w, d3, acc);

        // roll windows (full unroll -> register renaming, no MOVs)
        tp = tc; tc = tn;
        sLp = sLc; sLc = sLn;
        sRp = sRc; sRc = sRn;
    }

    // block reduction: warp shuffle tree, then one smem stage (deterministic)
#pragma unroll
    for (int s = 16; s > 0; s >>= 1)
        acc += __shfl_down_sync(0xffffffffu, acc, s);
    if (lane == 0) sred[tid >> 5] = acc;
    __syncthreads();
    if (tid == 0) {
        float r = 0.0f;
#pragma unroll
        for (int wrp = 0; wrp < THREADS_B / 32; wrp++) r += sred[wrp];
        g_partials[bid] = r;
        __threadfence();                       // publish partial before counting
        unsigned prev = atomicAdd(&g_done, 1u);
        s_last = (prev == GRID_B - 1u);
    }
    __syncthreads();

    // last block to finish folds the 2048 partials (fixed order -> deterministic)
    if (s_last) {
        float r = 0.0f;
#pragma unroll
        for (int k = 0; k < GRID_B / THREADS_B; k++)
            r += __ldcg(&g_partials[tid + k * THREADS_B]);   // L2-fresh reads
#pragma unroll
        for (int s = 16; s > 0; s >>= 1)
            r += __shfl_down_sync(0xffffffffu, r, s);
        if (lane == 0) sred[tid >> 5] = r;
        __syncthreads();
        if (tid == 0) {
            float tot = 0.0f;
#pragma unroll
            for (int wrp = 0; wrp < THREADS_B / 32; wrp++) tot += sred[wrp];
            out[0] = tot * (1.0f / (float)TOTAL);
            g_done = 0;                        // reset for next graph replay
        }
    }
}

extern "C" void kernel_launch(void* const* d_in, const int* in_sizes, int n_in,
                              void* d_out, int out_size) {
    const float* pred   = (const float*)d_in[0];
    const float* target = (const float*)d_in[1];
    (void)in_sizes; (void)n_in; (void)out_size;

    main_kernel<<<GRID_B, THREADS_B>>>(pred, target, (float*)d_out);
}